// round 4
// baseline (speedup 1.0000x reference)
#include <cuda_runtime.h>
#include <cstdint>

#define BB 64
#define NN 1024

// Output layout (flattened reference tuple, all float32):
#define OFF_DONE 0
#define OFF_NM   1
#define OFF_ADJ  (1 + BB*NN)
#define OFF_FA   (OFF_ADJ + (size_t)BB*NN*NN)
#define OFF_PT   (OFF_FA + BB)
#define OFF_STEP (OFF_PT + BB)

__device__ float g_fp[BB * NN];     // fpresent[b, i]
__device__ float g_dlast[NN];       // dist[:, N-1] contiguous
__device__ float g_nmlast[BB];      // new_mask[b, N-1] (for `done` reduction)

__global__ void k_prep(const float* __restrict__ inputs,
                       const float* __restrict__ dist,
                       const float* __restrict__ mask,
                       const float* __restrict__ ptime,
                       const int*   __restrict__ pres,
                       const int*   __restrict__ fut,
                       float* out)
{
    int b = blockIdx.x;
    int j = threadIdx.x;

    int   pa = pres[b];
    float pt = ptime[b];

    float4 in4 = *reinterpret_cast<const float4*>(inputs + ((size_t)(b * NN + j)) * 4);
    float op = in4.x, cl = in4.y, dur = in4.z;
    float T0 = inputs[3];

    float dlast  = dist[(size_t)j * NN + (NN - 1)];
    float arrive = dist[(size_t)pa * NN + j] + pt;
    float wait   = fmaxf(0.0f, op - arrive);
    float t      = arrive + wait;

    bool c1 = t <= cl;
    bool c2 = ((t + dur) + dlast) <= T0;

    float m = mask[b * NN + j];
    if (j == pa) m = 0.0f;
    float nm = (c1 && c2) ? m : 0.0f;

    float fpres = t + dur;

    out[OFF_NM + b * NN + j] = nm;
    g_fp[b * NN + j] = fpres;
    if (b == 0) g_dlast[j] = dlast;
    if (j == NN - 1) g_nmlast[b] = nm;

    int fb = fut[b];
    if (j == fb) out[OFF_PT + b] = fpres;
    if (j == 0) {
        out[OFF_FA + b]   = (float)fb;
        out[OFF_STEP + b] = 1.0f;
    }
}

// adj kernel, no smem:
//  - thread t (t<255) owns j = 3+4t .. 6+4t  → output float4 is 16B-aligned
//    (adj row base ≡ 1 mod 4 floats), new_mask float4 load is aligned too.
//  - thread 255 owns the leftover j ∈ {0,1,2,1023} (scalar stores).
//  - dist read via scalar __ldg; a block touches RR rows (32 KB) → L1-resident
//    across the BT batch loop.
#define BT 8
#define RR 8

__global__ __launch_bounds__(256, 5) void k_adj(const float* __restrict__ inputs,
                                                const float* __restrict__ dist,
                                                float* out)
{
    const int ITILES = NN / RR;                 // 128
    int itile = blockIdx.x & (ITILES - 1);
    int b0    = (blockIdx.x / ITILES) * BT;
    int i0    = itile * RR;
    int tid   = threadIdx.x;

    if (blockIdx.x == 0 && tid == 0) {
        float any = 0.0f;
#pragma unroll
        for (int b = 0; b < BB; b++) any = fmaxf(any, g_nmlast[b]);
        out[OFF_DONE] = (any > 0.0f) ? 0.0f : 1.0f;
    }

    const bool slot = (tid < 255);
    const int  jb   = 3 + 4 * tid;
    const int  js[4] = {0, 1, 2, NN - 1};

    float dl[4];
    if (slot) {
#pragma unroll
        for (int e = 0; e < 4; e++) dl[e] = g_dlast[jb + e];
    } else {
#pragma unroll
        for (int e = 0; e < 4; e++) dl[e] = g_dlast[js[e]];
    }

    const float* nm_base = out + OFF_NM;

    for (int bb = 0; bb < BT; bb++) {
        int b = b0 + bb;

        float op[4], cl[4], du[4], nm[4];
        if (slot) {
#pragma unroll
            for (int e = 0; e < 4; e++) {
                float4 in4 = *reinterpret_cast<const float4*>(
                    inputs + ((size_t)(b * NN + jb + e)) * 4);
                op[e] = in4.x; cl[e] = in4.y; du[e] = in4.z;
            }
            float4 nm4 = *reinterpret_cast<const float4*>(nm_base + b * NN + jb);
            nm[0] = nm4.x; nm[1] = nm4.y; nm[2] = nm4.z; nm[3] = nm4.w;
        } else {
#pragma unroll
            for (int e = 0; e < 4; e++) {
                float4 in4 = *reinterpret_cast<const float4*>(
                    inputs + ((size_t)(b * NN + js[e])) * 4);
                op[e] = in4.x; cl[e] = in4.y; du[e] = in4.z;
                nm[e] = nm_base[b * NN + js[e]];
            }
        }
        float Tb = inputs[((size_t)b * NN) * 4 + 3];

#pragma unroll
        for (int r = 0; r < RR; r++) {
            int   i  = i0 + r;
            float fp = g_fp[b * NN + i];
            const float* drow = dist + (size_t)i * NN;
            float* orow = out + OFF_ADJ + ((size_t)(b * NN + i)) * NN;

            if (slot) {
                float v[4];
#pragma unroll
                for (int e = 0; e < 4; e++) {
                    float arr2 = __ldg(drow + jb + e) + fp;
                    float w    = fmaxf(0.0f, op[e] - arr2);
                    float s    = arr2 + w;
                    bool a1 = s <= cl[e];
                    bool a2 = ((s + du[e]) + dl[e]) <= Tb;
                    float x = (a1 && a2) ? nm[e] : 0.0f;
                    if (jb + e == i) x = 1.0f;
                    v[e] = x;
                }
                *reinterpret_cast<float4*>(orow + jb) =
                    make_float4(v[0], v[1], v[2], v[3]);
            } else {
#pragma unroll
                for (int e = 0; e < 4; e++) {
                    int j = js[e];
                    float arr2 = __ldg(drow + j) + fp;
                    float w    = fmaxf(0.0f, op[e] - arr2);
                    float s    = arr2 + w;
                    bool a1 = s <= cl[e];
                    bool a2 = ((s + du[e]) + dl[e]) <= Tb;
                    float x = (a1 && a2) ? nm[e] : 0.0f;
                    if (j == i) x = 1.0f;
                    orow[j] = x;
                }
            }
        }
    }
}

extern "C" void kernel_launch(void* const* d_in, const int* in_sizes, int n_in,
                              void* d_out, int out_size)
{
    const float* inputs = (const float*)d_in[0];   // (B, N, 4) f32
    const float* dist   = (const float*)d_in[1];   // (N, N)   f32
    const float* mask   = (const float*)d_in[2];   // (B, N)   f32
    const float* ptime  = (const float*)d_in[3];   // (B, 1)   f32
    const int*   pres   = (const int*)d_in[4];     // (B,)     i32
    const int*   fut    = (const int*)d_in[5];     // (B,)     i32
    float* out = (float*)d_out;

    k_prep<<<BB, NN>>>(inputs, dist, mask, ptime, pres, fut, out);
    k_adj<<<(NN / RR) * (BB / BT), 256>>>(inputs, dist, out);
}

// round 5
// speedup vs baseline: 1.0464x; 1.0464x over previous
#include <cuda_runtime.h>
#include <cstdint>

#define BB 64
#define NN 1024

// Output layout (flattened reference tuple, all float32):
#define OFF_DONE 0
#define OFF_NM   1
#define OFF_ADJ  (1 + BB*NN)
#define OFF_FA   (OFF_ADJ + (size_t)BB*NN*NN)
#define OFF_PT   (OFF_FA + BB)
#define OFF_STEP (OFF_PT + BB)

__device__ float g_fp[BB * NN];     // fpresent[b, i]
__device__ float g_dlast[NN];       // dist[:, N-1] contiguous
__device__ float g_nmlast[BB];      // new_mask[b, N-1] (for `done` reduction)

__global__ void k_prep(const float* __restrict__ inputs,
                       const float* __restrict__ dist,
                       const float* __restrict__ mask,
                       const float* __restrict__ ptime,
                       const int*   __restrict__ pres,
                       const int*   __restrict__ fut,
                       float* out)
{
    int b = blockIdx.x;
    int j = threadIdx.x;

    int   pa = pres[b];
    float pt = ptime[b];

    float4 in4 = *reinterpret_cast<const float4*>(inputs + ((size_t)(b * NN + j)) * 4);
    float op = in4.x, cl = in4.y, dur = in4.z;
    float T0 = inputs[3];

    float dlast  = dist[(size_t)j * NN + (NN - 1)];
    float arrive = dist[(size_t)pa * NN + j] + pt;
    float wait   = fmaxf(0.0f, op - arrive);
    float t      = arrive + wait;

    bool c1 = t <= cl;
    bool c2 = ((t + dur) + dlast) <= T0;

    float m = mask[b * NN + j];
    if (j == pa) m = 0.0f;
    float nm = (c1 && c2) ? m : 0.0f;

    float fpres = t + dur;

    out[OFF_NM + b * NN + j] = nm;
    g_fp[b * NN + j] = fpres;
    if (b == 0) g_dlast[j] = dlast;
    if (j == NN - 1) g_nmlast[b] = nm;

    int fb = fut[b];
    if (j == fb) out[OFF_PT + b] = fpres;
    if (j == 0) {
        out[OFF_FA + b]   = (float)fb;
        out[OFF_STEP + b] = 1.0f;
    }
}

// adj kernel — R1 structure (fully coalesced, no smem), occupancy-capped.
// Block = (i-tile of RR rows) x (batch-tile of BT). Each thread handles
// j = tid + 256q, q=0..3 (coalesced loads AND stores).
#define BT 4
#define RR 8

__global__ __launch_bounds__(256, 6) void k_adj(const float* __restrict__ inputs,
                                                const float* __restrict__ dist,
                                                float* out)
{
    const int ITILES = NN / RR;                 // 128
    int itile = blockIdx.x & (ITILES - 1);
    int b0    = (blockIdx.x / ITILES) * BT;
    int i0    = itile * RR;
    int tid   = threadIdx.x;

    if (blockIdx.x == 0 && tid == 0) {
        float any = 0.0f;
#pragma unroll
        for (int b = 0; b < BB; b++) any = fmaxf(any, g_nmlast[b]);
        out[OFF_DONE] = (any > 0.0f) ? 0.0f : 1.0f;
    }

    float dl[4];
#pragma unroll
    for (int q = 0; q < 4; q++) dl[q] = g_dlast[tid + 256 * q];

    const float* nm_base = out + OFF_NM;

    for (int bb = 0; bb < BT; bb++) {
        int b = b0 + bb;

        float op[4], cl[4], du[4], nm[4];
#pragma unroll
        for (int q = 0; q < 4; q++) {
            int j = tid + 256 * q;
            float4 in4 = *reinterpret_cast<const float4*>(
                inputs + ((size_t)(b * NN + j)) * 4);
            op[q] = in4.x; cl[q] = in4.y; du[q] = in4.z;
            nm[q] = nm_base[b * NN + j];
        }
        float Tb = inputs[((size_t)b * NN) * 4 + 3];

#pragma unroll
        for (int r = 0; r < RR; r++) {
            int   i  = i0 + r;
            float fp = g_fp[b * NN + i];
            const float* drow = dist + (size_t)i * NN;
            float* orow = out + OFF_ADJ + ((size_t)(b * NN + i)) * NN;

#pragma unroll
            for (int q = 0; q < 4; q++) {
                int j = tid + 256 * q;
                float arr2 = drow[j] + fp;
                float w    = fmaxf(0.0f, op[q] - arr2);
                float s    = arr2 + w;
                bool a1 = s <= cl[q];
                bool a2 = ((s + du[q]) + dl[q]) <= Tb;
                float v = (a1 && a2) ? nm[q] : 0.0f;
                if (j == i) v = 1.0f;
                orow[j] = v;
            }
        }
    }
}

extern "C" void kernel_launch(void* const* d_in, const int* in_sizes, int n_in,
                              void* d_out, int out_size)
{
    const float* inputs = (const float*)d_in[0];   // (B, N, 4) f32
    const float* dist   = (const float*)d_in[1];   // (N, N)   f32
    const float* mask   = (const float*)d_in[2];   // (B, N)   f32
    const float* ptime  = (const float*)d_in[3];   // (B, 1)   f32
    const int*   pres   = (const int*)d_in[4];     // (B,)     i32
    const int*   fut    = (const int*)d_in[5];     // (B,)     i32
    float* out = (float*)d_out;

    k_prep<<<BB, NN>>>(inputs, dist, mask, ptime, pres, fut, out);
    k_adj<<<(NN / RR) * (BB / BT), 256>>>(inputs, dist, out);
}